// round 2
// baseline (speedup 1.0000x reference)
#include <cuda_runtime.h>
#include <math.h>

// Problem constants (B, F, S, D) = (16, 2048, 512, 256)
#define BB   16
#define FF   2048
#define SS   512
#define DD   256
#define D2   512    // 2*D (hidden width of edge MLP, width of H rows)
#define DLAT 512

#define NEDGE (BB*FF)

// ---------------- scratch (device globals; no allocation allowed) ----------
__device__ float g_NA[SS*D2];     // nodes @ W1[0:256]        (1 MB)
__device__ float g_NC[SS*D2];     // nodes @ W1[512:768]      (1 MB)
__device__ float g_PP[8*D2];      // pred_emb @ W1[256:512] + b1
__device__ float g_RC[8*D2];      // role_emb @ W1[512:768]
__device__ float g_H [BB*SS*D2];  // segment-summed gelu(pre) (16 MB)
__device__ float g_cnt[BB*SS];    // message counts per (b,node)
__device__ float g_pool[BB*DD];   // sum over S of layernormed x
__device__ float g_L1[BB*DLAT];   // gelu(pooled@Wl1+bl1)

__device__ __forceinline__ float gelu_f(float x) {
    return 0.5f * x * (1.0f + erff(x * 0.70710678118654752f));
}

// ---------------- 0: zero the accumulators --------------------------------
__global__ void zero_kernel() {
    int idx    = blockIdx.x * blockDim.x + threadIdx.x;
    int stride = gridDim.x * blockDim.x;
    float4 z = make_float4(0.f, 0.f, 0.f, 0.f);
    for (int i = idx; i < (BB*SS*D2)/4; i += stride) reinterpret_cast<float4*>(g_H)[i]    = z;
    for (int i = idx; i < (BB*SS)/4;    i += stride) reinterpret_cast<float4*>(g_cnt)[i]  = z;
    for (int i = idx; i < (BB*DD)/4;    i += stride) reinterpret_cast<float4*>(g_pool)[i] = z;
}

// ---------------- 1: NA = nodes@W1a, NC = nodes@W1c ------------------------
// grid 64 blocks (8 node rows each), 256 threads
__global__ __launch_bounds__(256) void precompute_nodes_kernel(
    const float* __restrict__ pos_emb, const float* __restrict__ W1)
{
    __shared__ float sn[8][DD];
    int r0  = blockIdx.x * 8;
    int tid = threadIdx.x;          // 0..255 == column j (and j+256)
    #pragma unroll
    for (int r = 0; r < 8; r++)
        sn[r][tid] = pos_emb[(r0 + r) * DD + tid];
    __syncthreads();

    float aA0[8], aA1[8], aC0[8], aC1[8];
    #pragma unroll
    for (int r = 0; r < 8; r++) { aA0[r]=0.f; aA1[r]=0.f; aC0[r]=0.f; aC1[r]=0.f; }

    int j = tid;
    #pragma unroll 4
    for (int k = 0; k < DD; k++) {
        float wa0 = W1[k*D2 + j];
        float wa1 = W1[k*D2 + j + 256];
        float wc0 = W1[(512 + k)*D2 + j];
        float wc1 = W1[(512 + k)*D2 + j + 256];
        #pragma unroll
        for (int r = 0; r < 8; r++) {
            float n = sn[r][k];
            aA0[r] = fmaf(n, wa0, aA0[r]);
            aA1[r] = fmaf(n, wa1, aA1[r]);
            aC0[r] = fmaf(n, wc0, aC0[r]);
            aC1[r] = fmaf(n, wc1, aC1[r]);
        }
    }
    #pragma unroll
    for (int r = 0; r < 8; r++) {
        g_NA[(r0+r)*D2 + j      ] = aA0[r];
        g_NA[(r0+r)*D2 + j + 256] = aA1[r];
        g_NC[(r0+r)*D2 + j      ] = aC0[r];
        g_NC[(r0+r)*D2 + j + 256] = aC1[r];
    }
}

// ---------------- 2: PP = pred_emb@W1p + b1, RC = role_emb@W1c -------------
// grid 16 blocks (rows 0-7: pred, 8-15: role), 512 threads
__global__ __launch_bounds__(512) void precompute_embs_kernel(
    const float* __restrict__ pred_emb, const float* __restrict__ role_emb,
    const float* __restrict__ W1, const float* __restrict__ b1)
{
    __shared__ float se[DD];
    int row = blockIdx.x;
    int j   = threadIdx.x;
    bool is_pred = (row < 8);
    const float* src = is_pred ? (pred_emb + row*DD) : (role_emb + (row-8)*DD);
    if (j < DD) se[j] = src[j];
    __syncthreads();

    const float* Wbase = is_pred ? (W1 + 256*D2) : (W1 + 512*D2);
    float acc = 0.f;
    #pragma unroll 4
    for (int k = 0; k < DD; k++)
        acc = fmaf(se[k], Wbase[k*D2 + j], acc);
    if (is_pred) g_PP[row*D2 + j]     = acc + b1[j];
    else         g_RC[(row-8)*D2 + j] = acc;
}

// ---------------- 3: edge kernel -------------------------------------------
// one block per edge, 128 threads; thread j handles 4 contiguous floats
__global__ __launch_bounds__(128) void edge_kernel(
    const int* __restrict__ a0, const int* __restrict__ a1,
    const int* __restrict__ pred, const int* __restrict__ role)
{
    int e = blockIdx.x;
    int b = e >> 11;                  // / FF (2048)
    int i0 = __ldg(&a0[e]);
    int i1 = __ldg(&a1[e]);
    int p  = __ldg(&pred[e]);
    bool is_role = (p == 1);
    bool do_bwd  = (p >= 2);          // !is_role && p != 0

    const float4* na0 = reinterpret_cast<const float4*>(g_NA + i0*D2);
    const float4* na1 = reinterpret_cast<const float4*>(g_NA + i1*D2);
    const float4* nc0 = reinterpret_cast<const float4*>(g_NC + i0*D2);
    const float4* pp  = reinterpret_cast<const float4*>(g_PP + p *D2);
    const float4* thirdp = is_role
        ? reinterpret_cast<const float4*>(g_RC + (__ldg(&role[e]) + 1)*D2)
        : reinterpret_cast<const float4*>(g_NC + i1*D2);
    int dst = is_role ? i0 : i1;
    float* Hf = g_H + (size_t)(b*SS + dst)*D2;
    float* Hb = g_H + (size_t)(b*SS + i0 )*D2;

    int j = threadIdx.x;              // 0..127, covers 512 floats as float4
    float4 va = na0[j];
    float4 vp = pp[j];
    float4 vt = thirdp[j];
    int jj = j * 4;
    atomicAdd(&Hf[jj+0], gelu_f(va.x + vp.x + vt.x));
    atomicAdd(&Hf[jj+1], gelu_f(va.y + vp.y + vt.y));
    atomicAdd(&Hf[jj+2], gelu_f(va.z + vp.z + vt.z));
    atomicAdd(&Hf[jj+3], gelu_f(va.w + vp.w + vt.w));
    if (do_bwd) {
        float4 vb = na1[j];
        float4 vc = nc0[j];
        atomicAdd(&Hb[jj+0], gelu_f(vb.x + vp.x + vc.x));
        atomicAdd(&Hb[jj+1], gelu_f(vb.y + vp.y + vc.y));
        atomicAdd(&Hb[jj+2], gelu_f(vb.z + vp.z + vc.z));
        atomicAdd(&Hb[jj+3], gelu_f(vb.w + vp.w + vc.w));
    }
    if (j == 0) {
        atomicAdd(&g_cnt[b*SS + dst], 1.0f);
        if (do_bwd) atomicAdd(&g_cnt[b*SS + i0], 1.0f);
    }
}

// ---------------- 4: node kernel: agg = H@W2 + cnt*b2; x = nodes+agg; ------
//                     layernorm; accumulate pooled sum
// grid (SS/16, BB) blocks, 256 threads; 16 nodes per block
__global__ __launch_bounds__(256) void node_kernel(
    const float* __restrict__ pos_emb, const float* __restrict__ W2,
    const float* __restrict__ b2, const float* __restrict__ ln_g,
    const float* __restrict__ ln_b)
{
    __shared__ float sbuf[16 * D2];   // 32 KB: phase1 = H tile, phase2 = x rows
    __shared__ float scnt[16];

    int b  = blockIdx.y;
    int s0 = blockIdx.x * 16;
    int d  = threadIdx.x;             // 0..255

    // load H tile [16][512]
    #pragma unroll
    for (int r = 0; r < 16; r++) {
        size_t base = (size_t)(b*SS + s0 + r) * D2;
        sbuf[r*D2 + d      ] = g_H[base + d      ];
        sbuf[r*D2 + d + 256] = g_H[base + d + 256];
    }
    if (d < 16) scnt[d] = g_cnt[b*SS + s0 + d];
    __syncthreads();

    // agg[r] = sum_k H[r][k] * W2[k][d]
    float agg[16];
    #pragma unroll
    for (int r = 0; r < 16; r++) agg[r] = 0.f;
    #pragma unroll 4
    for (int k = 0; k < D2; k++) {
        float w = W2[k*DD + d];
        #pragma unroll
        for (int r = 0; r < 16; r++)
            agg[r] = fmaf(sbuf[r*D2 + k], w, agg[r]);
    }
    __syncthreads();   // done reading H tile; reuse sbuf for x

    float bbias = b2[d];
    #pragma unroll
    for (int r = 0; r < 16; r++)
        sbuf[r*DD + d] = pos_emb[(s0 + r)*DD + d] + agg[r] + scnt[r]*bbias;
    __syncthreads();

    // layernorm: warp w handles rows 2w, 2w+1 (8 warps x 2 rows = 16)
    int warp = d >> 5, lane = d & 31;
    #pragma unroll
    for (int rr = 0; rr < 2; rr++) {
        int r = warp*2 + rr;
        float v[8];
        float sum = 0.f;
        #pragma unroll
        for (int q = 0; q < 8; q++) {
            v[q] = sbuf[r*DD + lane + q*32];
            sum += v[q];
        }
        #pragma unroll
        for (int o = 16; o > 0; o >>= 1) sum += __shfl_xor_sync(0xffffffffu, sum, o);
        float mu = sum * (1.f/DD);
        float sq = 0.f;
        #pragma unroll
        for (int q = 0; q < 8; q++) { float t = v[q] - mu; sq += t*t; }
        #pragma unroll
        for (int o = 16; o > 0; o >>= 1) sq += __shfl_xor_sync(0xffffffffu, sq, o);
        float rstd = rsqrtf(sq * (1.f/DD) + 1e-5f);
        #pragma unroll
        for (int q = 0; q < 8; q++) {
            int dd = lane + q*32;
            sbuf[r*DD + dd] = (v[q] - mu) * rstd * ln_g[dd] + ln_b[dd];
        }
    }
    __syncthreads();

    // partial pooled sum over the 16 rows, one atomic per (b,d) per block
    float ps = 0.f;
    #pragma unroll
    for (int r = 0; r < 16; r++) ps += sbuf[r*DD + d];
    atomicAdd(&g_pool[b*DD + d], ps);
}

// ---------------- 5: final MLP ---------------------------------------------
__global__ __launch_bounds__(512) void final1_kernel(
    const float* __restrict__ Wl1, const float* __restrict__ bl1)
{
    __shared__ float sp[DD];
    int b = blockIdx.x, j = threadIdx.x;
    if (j < DD) sp[j] = g_pool[b*DD + j] * (1.f / SS);   // pooled mean
    __syncthreads();
    float acc = bl1[j];
    #pragma unroll 4
    for (int k = 0; k < DD; k++)
        acc = fmaf(sp[k], Wl1[k*DLAT + j], acc);
    g_L1[b*DLAT + j] = gelu_f(acc);
}

__global__ __launch_bounds__(512) void final2_kernel(
    const float* __restrict__ Wl2, const float* __restrict__ bl2,
    float* __restrict__ out)
{
    __shared__ float sl[DLAT];
    int b = blockIdx.x, j = threadIdx.x;
    sl[j] = g_L1[b*DLAT + j];
    __syncthreads();
    float acc = bl2[j];
    #pragma unroll 4
    for (int k = 0; k < DLAT; k++)
        acc = fmaf(sl[k], Wl2[k*DLAT + j], acc);
    out[b*DLAT + j] = acc;
}

// ---------------- launch ----------------------------------------------------
extern "C" void kernel_launch(void* const* d_in, const int* in_sizes, int n_in,
                              void* d_out, int out_size)
{
    const int*   a0       = (const int*)  d_in[0];
    const int*   a1       = (const int*)  d_in[1];
    const int*   pred_idx = (const int*)  d_in[2];
    const int*   role_idx = (const int*)  d_in[3];
    // d_in[4] = seq_len (compile-time SS)
    const float* pos_emb  = (const float*)d_in[5];
    const float* pred_emb = (const float*)d_in[6];
    const float* role_emb = (const float*)d_in[7];
    const float* W1       = (const float*)d_in[8];
    const float* b1       = (const float*)d_in[9];
    const float* W2       = (const float*)d_in[10];
    const float* b2       = (const float*)d_in[11];
    const float* ln_g     = (const float*)d_in[12];
    const float* ln_b     = (const float*)d_in[13];
    const float* Wl1      = (const float*)d_in[14];
    const float* bl1      = (const float*)d_in[15];
    const float* Wl2      = (const float*)d_in[16];
    const float* bl2      = (const float*)d_in[17];
    float* out = (float*)d_out;

    zero_kernel<<<2048, 256>>>();
    precompute_nodes_kernel<<<SS/8, 256>>>(pos_emb, W1);
    precompute_embs_kernel<<<16, 512>>>(pred_emb, role_emb, W1, b1);
    edge_kernel<<<NEDGE, 128>>>(a0, a1, pred_idx, role_idx);
    dim3 ngrid(SS/16, BB);
    node_kernel<<<ngrid, 256>>>(pos_emb, W2, b2, ln_g, ln_b);
    final1_kernel<<<BB, DLAT>>>(Wl1, bl1);
    final2_kernel<<<BB, DLAT>>>(Wl2, bl2, out);
}

// round 5
// speedup vs baseline: 1.3143x; 1.3143x over previous
#include <cuda_runtime.h>
#include <math.h>

// Problem constants (B, F, S, D) = (16, 2048, 512, 256)
#define BB   16
#define FF   2048
#define SS   512
#define DD   256
#define D2   512    // 2*D (hidden width of edge MLP, width of H rows)
#define DLAT 512

#define NEDGE (BB*FF)

typedef unsigned long long ull;

// ---------------- scratch (device globals; no allocation allowed) ----------
__device__ float g_NA[SS*D2];     // nodes @ W1[0:256]        (1 MB)
__device__ float g_NC[SS*D2];     // nodes @ W1[512:768]      (1 MB)
__device__ float g_PP[8*D2];      // pred_emb @ W1[256:512] + b1
__device__ float g_RC[8*D2];      // role_emb @ W1[512:768]
__device__ float g_W2q[D2*DD];    // W2 repacked: [k/4][d][k%4]  (512 KB)
__device__ float g_H [BB*SS*D2];  // segment-summed gelu(pre) (16 MB)
__device__ float g_cnt[BB*SS];    // message counts per (b,node)
__device__ float g_pool[BB*DD];   // sum over S of layernormed x
__device__ float g_L1[BB*DLAT];   // gelu(pooled@Wl1+bl1)

__device__ __forceinline__ float gelu_f(float x) {
    return 0.5f * x * (1.0f + erff(x * 0.70710678118654752f));
}

// packed f32x2 fma: d = a*b + d  (elementwise on the two packed floats)
__device__ __forceinline__ void ffma2(ull& d, ull a, ull b) {
    asm("fma.rn.f32x2 %0, %1, %2, %3;" : "=l"(d) : "l"(a), "l"(b), "l"(d));
}
__device__ __forceinline__ ull pack2(float x, float y) {
    ull r; asm("mov.b64 %0, {%1, %2};" : "=l"(r) : "f"(x), "f"(y)); return r;
}
__device__ __forceinline__ float2 unpack2(ull v) {
    float2 r; asm("mov.b64 {%0, %1}, %2;" : "=f"(r.x), "=f"(r.y) : "l"(v)); return r;
}
// 128-bit vector reduction (sm_90+): 1 instruction instead of 4 atomicAdd
__device__ __forceinline__ void red_add_v4(float* addr, float4 v) {
    asm volatile("red.global.add.v4.f32 [%0], {%1, %2, %3, %4};"
                 :: "l"(addr), "f"(v.x), "f"(v.y), "f"(v.z), "f"(v.w) : "memory");
}

// ---------------- 1: merged prep kernel ------------------------------------
// grid = 512 blocks x 256 threads; block roles:
//   [0,64):    NA/NC precompute (8 node rows each, f32x2)
//   [64,80):   PP (rows 0-7) / RC (rows 8-15)
//   [80,96):   W2q repack
//   [96,512):  zero g_H, g_cnt, g_pool
__global__ __launch_bounds__(256) void prep_kernel(
    const float* __restrict__ pos_emb, const float* __restrict__ pred_emb,
    const float* __restrict__ role_emb, const float* __restrict__ W1,
    const float* __restrict__ b1, const float* __restrict__ W2)
{
    __shared__ float sh[8*DD];
    int bid = blockIdx.x;
    int tid = threadIdx.x;

    if (bid < 64) {
        // ---- NA = nodes@W1a, NC = nodes@W1c, rows [bid*8, bid*8+8) ----
        int r0 = bid * 8;
        #pragma unroll
        for (int r = 0; r < 8; r++)
            sh[r*DD + tid] = pos_emb[(r0 + r)*DD + tid];
        __syncthreads();

        ull aA[8], aC[8];
        #pragma unroll
        for (int r = 0; r < 8; r++) { aA[r] = 0ull; aC[r] = 0ull; }
        int j2 = 2*tid;   // column pair (2*tid, 2*tid+1)
        #pragma unroll 2
        for (int k = 0; k < DD; k++) {
            ull wa = *reinterpret_cast<const ull*>(W1 + (size_t)k*D2 + j2);
            ull wc = *reinterpret_cast<const ull*>(W1 + (size_t)(512 + k)*D2 + j2);
            #pragma unroll
            for (int r = 0; r < 8; r++) {
                float h = sh[r*DD + k];
                ull hp = pack2(h, h);
                ffma2(aA[r], hp, wa);
                ffma2(aC[r], hp, wc);
            }
        }
        #pragma unroll
        for (int r = 0; r < 8; r++) {
            *reinterpret_cast<ull*>(g_NA + (r0+r)*D2 + j2) = aA[r];
            *reinterpret_cast<ull*>(g_NC + (r0+r)*D2 + j2) = aC[r];
        }
    } else if (bid < 80) {
        // ---- PP = pred_emb@W1p + b1 (rows 0-7), RC = role_emb@W1c (8-15) ----
        int row = bid - 64;
        bool is_pred = (row < 8);
        const float* src = is_pred ? (pred_emb + row*DD) : (role_emb + (row-8)*DD);
        sh[tid] = src[tid];
        __syncthreads();

        const float* Wbase = is_pred ? (W1 + 256*D2) : (W1 + 512*D2);
        ull acc = 0ull;
        int j2 = 2*tid;
        #pragma unroll 4
        for (int k = 0; k < DD; k++) {
            ull w = *reinterpret_cast<const ull*>(Wbase + (size_t)k*D2 + j2);
            float s = sh[k];
            ffma2(acc, pack2(s, s), w);
        }
        float2 a = unpack2(acc);
        if (is_pred) {
            g_PP[row*D2 + j2    ] = a.x + b1[j2];
            g_PP[row*D2 + j2 + 1] = a.y + b1[j2+1];
        } else {
            g_RC[(row-8)*D2 + j2    ] = a.x;
            g_RC[(row-8)*D2 + j2 + 1] = a.y;
        }
    } else if (bid < 96) {
        // ---- repack W2 -> W2q[k4*1024 + d*4 + kk] = W2[(k4*4+kk)*DD + d] ----
        for (int i = (bid - 80)*256 + tid; i < D2*DD; i += 16*256) {
            int k4  = i >> 10;
            int rem = i & 1023;
            int d   = rem >> 2;
            int kk  = rem & 3;
            g_W2q[i] = W2[(k4*4 + kk)*DD + d];
        }
    } else {
        // ---- zero accumulators ----
        int idx    = (bid - 96)*256 + tid;
        int stride = (512 - 96)*256;
        float4 z = make_float4(0.f, 0.f, 0.f, 0.f);
        for (int i = idx; i < (BB*SS*D2)/4; i += stride) reinterpret_cast<float4*>(g_H)[i]    = z;
        for (int i = idx; i < (BB*SS)/4;    i += stride) reinterpret_cast<float4*>(g_cnt)[i]  = z;
        for (int i = idx; i < (BB*DD)/4;    i += stride) reinterpret_cast<float4*>(g_pool)[i] = z;
    }
}

// ---------------- 2: edge kernel -------------------------------------------
// 128 threads, 4 edges per block; thread j handles 4 contiguous floats.
__global__ __launch_bounds__(128) void edge_kernel(
    const int* __restrict__ a0, const int* __restrict__ a1,
    const int* __restrict__ pred, const int* __restrict__ role)
{
    int j  = threadIdx.x;              // 0..127
    int e0 = blockIdx.x * 4;

    #pragma unroll
    for (int t = 0; t < 4; t++) {
        int e = e0 + t;
        int b = e >> 11;                  // / FF
        int i0 = __ldg(&a0[e]);
        int i1 = __ldg(&a1[e]);
        int p  = __ldg(&pred[e]);
        bool is_role = (p == 1);
        bool do_bwd  = (p >= 2);

        const float4* na0 = reinterpret_cast<const float4*>(g_NA + i0*D2);
        const float4* pp  = reinterpret_cast<const float4*>(g_PP + p *D2);
        const float4* thirdp = is_role
            ? reinterpret_cast<const float4*>(g_RC + (__ldg(&role[e]) + 1)*D2)
            : reinterpret_cast<const float4*>(g_NC + i1*D2);
        int dst = is_role ? i0 : i1;
        float* Hf = g_H + (size_t)(b*SS + dst)*D2;

        float4 va = na0[j];
        float4 vp = pp[j];
        float4 vt = thirdp[j];
        float4 g;
        g.x = gelu_f(va.x + vp.x + vt.x);
        g.y = gelu_f(va.y + vp.y + vt.y);
        g.z = gelu_f(va.z + vp.z + vt.z);
        g.w = gelu_f(va.w + vp.w + vt.w);
        red_add_v4(Hf + 4*j, g);

        if (do_bwd) {
            const float4* na1 = reinterpret_cast<const float4*>(g_NA + i1*D2);
            const float4* nc0 = reinterpret_cast<const float4*>(g_NC + i0*D2);
            float* Hb = g_H + (size_t)(b*SS + i0)*D2;
            float4 vb = na1[j];
            float4 vc = nc0[j];
            float4 h;
            h.x = gelu_f(vb.x + vp.x + vc.x);
            h.y = gelu_f(vb.y + vp.y + vc.y);
            h.z = gelu_f(vb.z + vp.z + vc.z);
            h.w = gelu_f(vb.w + vp.w + vc.w);
            red_add_v4(Hb + 4*j, h);
        }
        if (j == 0) {
            atomicAdd(&g_cnt[b*SS + dst], 1.0f);
            if (do_bwd) atomicAdd(&g_cnt[b*SS + i0], 1.0f);
        }
    }
}

// ---------------- 3: node kernel: agg = H@W2 + cnt*b2; x = nodes+agg; ------
//                     layernorm; accumulate pooled sum.  f32x2 GEMM.
// grid (SS/16, BB) blocks, 256 threads; 16 nodes per block, thread = column d
__global__ __launch_bounds__(256) void node_kernel(
    const float* __restrict__ pos_emb, const float* __restrict__ b2,
    const float* __restrict__ ln_g, const float* __restrict__ ln_b)
{
    __shared__ float sbuf[16 * D2];   // 32 KB: phase1 = H tile, phase2 = x rows
    __shared__ float scnt[16];

    int b  = blockIdx.y;
    int s0 = blockIdx.x * 16;
    int d  = threadIdx.x;             // 0..255

    // load H tile [16][512] = 2048 float4, 8 per thread
    {
        const float4* Hv = reinterpret_cast<const float4*>(g_H + (size_t)(b*SS + s0)*D2);
        float4* sv = reinterpret_cast<float4*>(sbuf);
        #pragma unroll
        for (int i = 0; i < 8; i++) sv[d + i*256] = Hv[d + i*256];
    }
    if (d < 16) scnt[d] = g_cnt[b*SS + s0 + d];
    __syncthreads();

    // agg[r][d] = sum_k H[r][k] * W2[k][d], packed over (k even, k odd)
    ull acc[16];
    #pragma unroll
    for (int r = 0; r < 16; r++) acc[r] = 0ull;

    #pragma unroll 2
    for (int k4 = 0; k4 < D2/4; k4++) {
        // 4 consecutive k's of column d: W2q[k4*1024 + d*4 .. +3]
        ulonglong2 wq = *reinterpret_cast<const ulonglong2*>(g_W2q + k4*1024 + d*4);
        #pragma unroll
        for (int r = 0; r < 16; r++) {
            ulonglong2 hq = *reinterpret_cast<const ulonglong2*>(sbuf + r*D2 + k4*4);
            ffma2(acc[r], hq.x, wq.x);
            ffma2(acc[r], hq.y, wq.y);
        }
    }
    __syncthreads();   // done reading H tile; reuse sbuf for x

    float bbias = b2[d];
    #pragma unroll
    for (int r = 0; r < 16; r++) {
        float2 a = unpack2(acc[r]);
        sbuf[r*DD + d] = pos_emb[(s0 + r)*DD + d] + (a.x + a.y) + scnt[r]*bbias;
    }
    __syncthreads();

    // layernorm: warp w handles rows 2w, 2w+1 (8 warps x 2 rows = 16)
    int warp = d >> 5, lane = d & 31;
    #pragma unroll
    for (int rr = 0; rr < 2; rr++) {
        int r = warp*2 + rr;
        float v[8];
        float sum = 0.f;
        #pragma unroll
        for (int q = 0; q < 8; q++) {
            v[q] = sbuf[r*DD + lane + q*32];
            sum += v[q];
        }
        #pragma unroll
        for (int o = 16; o > 0; o >>= 1) sum += __shfl_xor_sync(0xffffffffu, sum, o);
        float mu = sum * (1.f/DD);
        float sq = 0.f;
        #pragma unroll
        for (int q = 0; q < 8; q++) { float tq = v[q] - mu; sq += tq*tq; }
        #pragma unroll
        for (int o = 16; o > 0; o >>= 1) sq += __shfl_xor_sync(0xffffffffu, sq, o);
        float rstd = rsqrtf(sq * (1.f/DD) + 1e-5f);
        #pragma unroll
        for (int q = 0; q < 8; q++) {
            int dd = lane + q*32;
            sbuf[r*DD + dd] = (v[q] - mu) * rstd * ln_g[dd] + ln_b[dd];
        }
    }
    __syncthreads();

    // partial pooled sum over the 16 rows, one atomic per (b,d) per block
    float ps = 0.f;
    #pragma unroll
    for (int r = 0; r < 16; r++) ps += sbuf[r*DD + d];
    atomicAdd(&g_pool[b*DD + d], ps);
}

// ---------------- 4: final MLP ---------------------------------------------
__global__ __launch_bounds__(512) void final1_kernel(
    const float* __restrict__ Wl1, const float* __restrict__ bl1)
{
    __shared__ float sp[DD];
    int b = blockIdx.x, j = threadIdx.x;
    if (j < DD) sp[j] = g_pool[b*DD + j] * (1.f / SS);   // pooled mean
    __syncthreads();
    float acc = bl1[j];
    #pragma unroll 4
    for (int k = 0; k < DD; k++)
        acc = fmaf(sp[k], Wl1[k*DLAT + j], acc);
    g_L1[b*DLAT + j] = gelu_f(acc);
}

__global__ __launch_bounds__(512) void final2_kernel(
    const float* __restrict__ Wl2, const float* __restrict__ bl2,
    float* __restrict__ out)
{
    __shared__ float sl[DLAT];
    int b = blockIdx.x, j = threadIdx.x;
    sl[j] = g_L1[b*DLAT + j];
    __syncthreads();
    float acc = bl2[j];
    #pragma unroll 4
    for (int k = 0; k < DLAT; k++)
        acc = fmaf(sl[k], Wl2[k*DLAT + j], acc);
    out[b*DLAT + j] = acc;
}

// ---------------- launch ----------------------------------------------------
extern "C" void kernel_launch(void* const* d_in, const int* in_sizes, int n_in,
                              void* d_out, int out_size)
{
    const int*   a0       = (const int*)  d_in[0];
    const int*   a1       = (const int*)  d_in[1];
    const int*   pred_idx = (const int*)  d_in[2];
    const int*   role_idx = (const int*)  d_in[3];
    // d_in[4] = seq_len (compile-time SS)
    const float* pos_emb  = (const float*)d_in[5];
    const float* pred_emb = (const float*)d_in[6];
    const float* role_emb = (const float*)d_in[7];
    const float* W1       = (const float*)d_in[8];
    const float* b1       = (const float*)d_in[9];
    const float* W2       = (const float*)d_in[10];
    const float* b2       = (const float*)d_in[11];
    const float* ln_g     = (const float*)d_in[12];
    const float* ln_b     = (const float*)d_in[13];
    const float* Wl1      = (const float*)d_in[14];
    const float* bl1      = (const float*)d_in[15];
    const float* Wl2      = (const float*)d_in[16];
    const float* bl2      = (const float*)d_in[17];
    float* out = (float*)d_out;

    prep_kernel<<<512, 256>>>(pos_emb, pred_emb, role_emb, W1, b1, W2);
    edge_kernel<<<NEDGE/4, 128>>>(a0, a1, pred_idx, role_idx);
    dim3 ngrid(SS/16, BB);
    node_kernel<<<ngrid, 256>>>(pos_emb, b2, ln_g, ln_b);
    final1_kernel<<<BB, DLAT>>>(Wl1, bl1);
    final2_kernel<<<BB, DLAT>>>(Wl2, bl2, out);
}

// round 6
// speedup vs baseline: 1.5981x; 1.2159x over previous
#include <cuda_runtime.h>
#include <math.h>

// Problem constants (B, F, S, D) = (16, 2048, 512, 256)
#define BB   16
#define FF   2048
#define SS   512
#define DD   256
#define D2   512    // 2*D (hidden width of edge MLP, width of H rows)
#define DLAT 512

#define NEDGE (BB*FF)

typedef unsigned long long ull;

// ---------------- scratch (device globals; no allocation allowed) ----------
__device__ float g_NA[SS*D2];     // nodes @ W1[0:256]        (1 MB)
__device__ float g_NC[SS*D2];     // nodes @ W1[512:768]      (1 MB)
__device__ float g_PP[8*D2];      // pred_emb @ W1[256:512] + b1
__device__ float g_RC[8*D2];      // role_emb @ W1[512:768]
__device__ float g_W2q[D2*DD];    // W2 repacked: [k/4][d][k%4]  (512 KB)
__device__ float g_H [BB*SS*D2];  // segment-summed gelu(pre) (16 MB)
__device__ float g_cnt[BB*SS];    // message counts per (b,node)
__device__ float g_pool[BB*DD];   // sum over S of layernormed x
__device__ float g_L1raw[BB*DLAT];// split-K partial sums of pooled@Wl1
__device__ float g_L1[BB*DLAT];   // gelu(pooled@Wl1+bl1)

__device__ __forceinline__ float gelu_f(float x) {
    return 0.5f * x * (1.0f + erff(x * 0.70710678118654752f));
}

// packed f32x2 fma: d = a*b + d  (elementwise on the two packed floats)
__device__ __forceinline__ void ffma2(ull& d, ull a, ull b) {
    asm("fma.rn.f32x2 %0, %1, %2, %3;" : "=l"(d) : "l"(a), "l"(b), "l"(d));
}
__device__ __forceinline__ ull pack2(float x, float y) {
    ull r; asm("mov.b64 %0, {%1, %2};" : "=l"(r) : "f"(x), "f"(y)); return r;
}
__device__ __forceinline__ float2 unpack2(ull v) {
    float2 r; asm("mov.b64 {%0, %1}, %2;" : "=f"(r.x), "=f"(r.y) : "l"(v)); return r;
}
// 128-bit vector reduction (sm_90+): 1 instruction instead of 4 atomicAdd
__device__ __forceinline__ void red_add_v4(float* addr, float4 v) {
    asm volatile("red.global.add.v4.f32 [%0], {%1, %2, %3, %4};"
                 :: "l"(addr), "f"(v.x), "f"(v.y), "f"(v.z), "f"(v.w) : "memory");
}

// ---------------- 1: merged prep kernel ------------------------------------
// grid = 512 blocks x 256 threads; block roles:
//   [0,64):    NA/NC precompute (8 node rows each, f32x2)
//   [64,80):   PP (rows 0-7) / RC (rows 8-15)
//   [80,96):   W2q repack
//   [96,512):  zero g_H, g_cnt, g_pool, g_L1raw
__global__ __launch_bounds__(256) void prep_kernel(
    const float* __restrict__ pos_emb, const float* __restrict__ pred_emb,
    const float* __restrict__ role_emb, const float* __restrict__ W1,
    const float* __restrict__ b1, const float* __restrict__ W2)
{
    __shared__ float sh[8*DD];
    int bid = blockIdx.x;
    int tid = threadIdx.x;

    if (bid < 64) {
        // ---- NA = nodes@W1a, NC = nodes@W1c, rows [bid*8, bid*8+8) ----
        int r0 = bid * 8;
        #pragma unroll
        for (int r = 0; r < 8; r++)
            sh[r*DD + tid] = pos_emb[(r0 + r)*DD + tid];
        __syncthreads();

        ull aA[8], aC[8];
        #pragma unroll
        for (int r = 0; r < 8; r++) { aA[r] = 0ull; aC[r] = 0ull; }
        int j2 = 2*tid;   // column pair (2*tid, 2*tid+1)
        #pragma unroll 2
        for (int k = 0; k < DD; k++) {
            ull wa = *reinterpret_cast<const ull*>(W1 + (size_t)k*D2 + j2);
            ull wc = *reinterpret_cast<const ull*>(W1 + (size_t)(512 + k)*D2 + j2);
            #pragma unroll
            for (int r = 0; r < 8; r++) {
                float h = sh[r*DD + k];
                ull hp = pack2(h, h);
                ffma2(aA[r], hp, wa);
                ffma2(aC[r], hp, wc);
            }
        }
        #pragma unroll
        for (int r = 0; r < 8; r++) {
            *reinterpret_cast<ull*>(g_NA + (r0+r)*D2 + j2) = aA[r];
            *reinterpret_cast<ull*>(g_NC + (r0+r)*D2 + j2) = aC[r];
        }
    } else if (bid < 80) {
        // ---- PP = pred_emb@W1p + b1 (rows 0-7), RC = role_emb@W1c (8-15) ----
        int row = bid - 64;
        bool is_pred = (row < 8);
        const float* src = is_pred ? (pred_emb + row*DD) : (role_emb + (row-8)*DD);
        sh[tid] = src[tid];
        __syncthreads();

        const float* Wbase = is_pred ? (W1 + 256*D2) : (W1 + 512*D2);
        ull acc = 0ull;
        int j2 = 2*tid;
        #pragma unroll 4
        for (int k = 0; k < DD; k++) {
            ull w = *reinterpret_cast<const ull*>(Wbase + (size_t)k*D2 + j2);
            float s = sh[k];
            ffma2(acc, pack2(s, s), w);
        }
        float2 a = unpack2(acc);
        if (is_pred) {
            g_PP[row*D2 + j2    ] = a.x + b1[j2];
            g_PP[row*D2 + j2 + 1] = a.y + b1[j2+1];
        } else {
            g_RC[(row-8)*D2 + j2    ] = a.x;
            g_RC[(row-8)*D2 + j2 + 1] = a.y;
        }
    } else if (bid < 96) {
        // ---- repack W2 -> W2q[k4*1024 + d*4 + kk] = W2[(k4*4+kk)*DD + d] ----
        for (int i = (bid - 80)*256 + tid; i < D2*DD; i += 16*256) {
            int k4  = i >> 10;
            int rem = i & 1023;
            int d   = rem >> 2;
            int kk  = rem & 3;
            g_W2q[i] = W2[(k4*4 + kk)*DD + d];
        }
    } else {
        // ---- zero accumulators ----
        int idx    = (bid - 96)*256 + tid;
        int stride = (512 - 96)*256;
        float4 z = make_float4(0.f, 0.f, 0.f, 0.f);
        for (int i = idx; i < (BB*SS*D2)/4; i += stride) reinterpret_cast<float4*>(g_H)[i]     = z;
        for (int i = idx; i < (BB*SS)/4;    i += stride) reinterpret_cast<float4*>(g_cnt)[i]   = z;
        for (int i = idx; i < (BB*DD)/4;    i += stride) reinterpret_cast<float4*>(g_pool)[i]  = z;
        for (int i = idx; i < (BB*DLAT)/4;  i += stride) reinterpret_cast<float4*>(g_L1raw)[i] = z;
    }
}

// ---------------- 2: edge kernel -------------------------------------------
// 128 threads, 4 edges per block; thread j handles 4 contiguous floats.
__global__ __launch_bounds__(128) void edge_kernel(
    const int* __restrict__ a0, const int* __restrict__ a1,
    const int* __restrict__ pred, const int* __restrict__ role)
{
    int j  = threadIdx.x;              // 0..127
    int e0 = blockIdx.x * 4;

    #pragma unroll
    for (int t = 0; t < 4; t++) {
        int e = e0 + t;
        int b = e >> 11;                  // / FF
        int i0 = __ldg(&a0[e]);
        int i1 = __ldg(&a1[e]);
        int p  = __ldg(&pred[e]);
        bool is_role = (p == 1);
        bool do_bwd  = (p >= 2);

        const float4* na0 = reinterpret_cast<const float4*>(g_NA + i0*D2);
        const float4* pp  = reinterpret_cast<const float4*>(g_PP + p *D2);
        const float4* thirdp = is_role
            ? reinterpret_cast<const float4*>(g_RC + (__ldg(&role[e]) + 1)*D2)
            : reinterpret_cast<const float4*>(g_NC + i1*D2);
        int dst = is_role ? i0 : i1;
        float* Hf = g_H + (size_t)(b*SS + dst)*D2;

        float4 va = na0[j];
        float4 vp = pp[j];
        float4 vt = thirdp[j];
        float4 g;
        g.x = gelu_f(va.x + vp.x + vt.x);
        g.y = gelu_f(va.y + vp.y + vt.y);
        g.z = gelu_f(va.z + vp.z + vt.z);
        g.w = gelu_f(va.w + vp.w + vt.w);
        red_add_v4(Hf + 4*j, g);

        if (do_bwd) {
            const float4* na1 = reinterpret_cast<const float4*>(g_NA + i1*D2);
            const float4* nc0 = reinterpret_cast<const float4*>(g_NC + i0*D2);
            float* Hb = g_H + (size_t)(b*SS + i0)*D2;
            float4 vb = na1[j];
            float4 vc = nc0[j];
            float4 h;
            h.x = gelu_f(vb.x + vp.x + vc.x);
            h.y = gelu_f(vb.y + vp.y + vc.y);
            h.z = gelu_f(vb.z + vp.z + vc.z);
            h.w = gelu_f(vb.w + vp.w + vc.w);
            red_add_v4(Hb + 4*j, h);
        }
        if (j == 0) {
            atomicAdd(&g_cnt[b*SS + dst], 1.0f);
            if (do_bwd) atomicAdd(&g_cnt[b*SS + i0], 1.0f);
        }
    }
}

// ---------------- 3: node kernel: agg = H@W2 + cnt*b2; x = nodes+agg; ------
//                     layernorm; accumulate pooled sum.  f32x2 GEMM.
// grid (SS/16, BB) blocks, 256 threads; 16 nodes per block, thread = column d
__global__ __launch_bounds__(256) void node_kernel(
    const float* __restrict__ pos_emb, const float* __restrict__ b2,
    const float* __restrict__ ln_g, const float* __restrict__ ln_b)
{
    __shared__ float sbuf[16 * D2];   // 32 KB: phase1 = H tile, phase2 = x rows
    __shared__ float scnt[16];

    int b  = blockIdx.y;
    int s0 = blockIdx.x * 16;
    int d  = threadIdx.x;             // 0..255

    // load H tile [16][512] = 2048 float4, 8 per thread
    {
        const float4* Hv = reinterpret_cast<const float4*>(g_H + (size_t)(b*SS + s0)*D2);
        float4* sv = reinterpret_cast<float4*>(sbuf);
        #pragma unroll
        for (int i = 0; i < 8; i++) sv[d + i*256] = Hv[d + i*256];
    }
    if (d < 16) scnt[d] = g_cnt[b*SS + s0 + d];
    __syncthreads();

    // agg[r][d] = sum_k H[r][k] * W2[k][d], packed over (k even, k odd)
    ull acc[16];
    #pragma unroll
    for (int r = 0; r < 16; r++) acc[r] = 0ull;

    #pragma unroll 2
    for (int k4 = 0; k4 < D2/4; k4++) {
        // 4 consecutive k's of column d: W2q[k4*1024 + d*4 .. +3]
        ulonglong2 wq = *reinterpret_cast<const ulonglong2*>(g_W2q + k4*1024 + d*4);
        #pragma unroll
        for (int r = 0; r < 16; r++) {
            ulonglong2 hq = *reinterpret_cast<const ulonglong2*>(sbuf + r*D2 + k4*4);
            ffma2(acc[r], hq.x, wq.x);
            ffma2(acc[r], hq.y, wq.y);
        }
    }
    __syncthreads();   // done reading H tile; reuse sbuf for x

    float bbias = b2[d];
    #pragma unroll
    for (int r = 0; r < 16; r++) {
        float2 a = unpack2(acc[r]);
        sbuf[r*DD + d] = pos_emb[(s0 + r)*DD + d] + (a.x + a.y) + scnt[r]*bbias;
    }
    __syncthreads();

    // layernorm: warp w handles rows 2w, 2w+1 (8 warps x 2 rows = 16)
    int warp = d >> 5, lane = d & 31;
    #pragma unroll
    for (int rr = 0; rr < 2; rr++) {
        int r = warp*2 + rr;
        float v[8];
        float sum = 0.f;
        #pragma unroll
        for (int q = 0; q < 8; q++) {
            v[q] = sbuf[r*DD + lane + q*32];
            sum += v[q];
        }
        #pragma unroll
        for (int o = 16; o > 0; o >>= 1) sum += __shfl_xor_sync(0xffffffffu, sum, o);
        float mu = sum * (1.f/DD);
        float sq = 0.f;
        #pragma unroll
        for (int q = 0; q < 8; q++) { float tq = v[q] - mu; sq += tq*tq; }
        #pragma unroll
        for (int o = 16; o > 0; o >>= 1) sq += __shfl_xor_sync(0xffffffffu, sq, o);
        float rstd = rsqrtf(sq * (1.f/DD) + 1e-5f);
        #pragma unroll
        for (int q = 0; q < 8; q++) {
            int dd = lane + q*32;
            sbuf[r*DD + dd] = (v[q] - mu) * rstd * ln_g[dd] + ln_b[dd];
        }
    }
    __syncthreads();

    // partial pooled sum over the 16 rows, one atomic per (b,d) per block
    float ps = 0.f;
    #pragma unroll
    for (int r = 0; r < 16; r++) ps += sbuf[r*DD + d];
    atomicAdd(&g_pool[b*DD + d], ps);
}

// ---------------- 4: final MLP, split-K across the chip ---------------------
// F1: grid (BB, 8) — k-slice of 32; 512 threads = column j.
__global__ __launch_bounds__(512) void final1_kernel(
    const float* __restrict__ Wl1)
{
    __shared__ float sp[32];
    int b  = blockIdx.x;
    int k0 = blockIdx.y * 32;
    int j  = threadIdx.x;
    if (j < 32) sp[j] = g_pool[b*DD + k0 + j] * (1.f / SS);   // pooled mean slice
    __syncthreads();
    float acc = 0.f;
    #pragma unroll
    for (int k = 0; k < 32; k++)
        acc = fmaf(sp[k], Wl1[(size_t)(k0 + k)*DLAT + j], acc);
    atomicAdd(&g_L1raw[b*DLAT + j], acc);
}

// F2: bias + gelu; also initialize out with bl2 (out is poisoned pre-timing).
__global__ __launch_bounds__(512) void final_mid_kernel(
    const float* __restrict__ bl1, const float* __restrict__ bl2,
    float* __restrict__ out)
{
    int b = blockIdx.x, j = threadIdx.x;
    g_L1[b*DLAT + j] = gelu_f(g_L1raw[b*DLAT + j] + bl1[j]);
    out[b*DLAT + j]  = bl2[j];
}

// F3: grid (BB, 8) — k-slice of 64; 512 threads = column j; accumulate into out.
__global__ __launch_bounds__(512) void final2_kernel(
    const float* __restrict__ Wl2, float* __restrict__ out)
{
    __shared__ float sl[64];
    int b  = blockIdx.x;
    int k0 = blockIdx.y * 64;
    int j  = threadIdx.x;
    if (j < 64) sl[j] = g_L1[b*DLAT + k0 + j];
    __syncthreads();
    float acc = 0.f;
    #pragma unroll
    for (int k = 0; k < 64; k++)
        acc = fmaf(sl[k], Wl2[(size_t)(k0 + k)*DLAT + j], acc);
    atomicAdd(&out[b*DLAT + j], acc);
}

// ---------------- launch ----------------------------------------------------
extern "C" void kernel_launch(void* const* d_in, const int* in_sizes, int n_in,
                              void* d_out, int out_size)
{
    const int*   a0       = (const int*)  d_in[0];
    const int*   a1       = (const int*)  d_in[1];
    const int*   pred_idx = (const int*)  d_in[2];
    const int*   role_idx = (const int*)  d_in[3];
    // d_in[4] = seq_len (compile-time SS)
    const float* pos_emb  = (const float*)d_in[5];
    const float* pred_emb = (const float*)d_in[6];
    const float* role_emb = (const float*)d_in[7];
    const float* W1       = (const float*)d_in[8];
    const float* b1       = (const float*)d_in[9];
    const float* W2       = (const float*)d_in[10];
    const float* b2       = (const float*)d_in[11];
    const float* ln_g     = (const float*)d_in[12];
    const float* ln_b     = (const float*)d_in[13];
    const float* Wl1      = (const float*)d_in[14];
    const float* bl1      = (const float*)d_in[15];
    const float* Wl2      = (const float*)d_in[16];
    const float* bl2      = (const float*)d_in[17];
    float* out = (float*)d_out;

    prep_kernel<<<512, 256>>>(pos_emb, pred_emb, role_emb, W1, b1, W2);
    edge_kernel<<<NEDGE/4, 128>>>(a0, a1, pred_idx, role_idx);
    dim3 ngrid(SS/16, BB);
    node_kernel<<<ngrid, 256>>>(pos_emb, b2, ln_g, ln_b);
    dim3 f1grid(BB, 8);
    final1_kernel<<<f1grid, DLAT>>>(Wl1);
    final_mid_kernel<<<BB, DLAT>>>(bl1, bl2, out);
    dim3 f2grid(BB, 8);
    final2_kernel<<<f2grid, DLAT>>>(Wl2, out);
}